// round 8
// baseline (speedup 1.0000x reference)
#include <cuda_runtime.h>
#include <cuda_fp16.h>

// ---------------- problem constants ----------------
#define N_NODES 10000
#define N_RELS  50
#define R_AUG   101                    // 2*N_RELS + 1
#define D       128
#define N_EDGES 320000
#define E_AUG   (2*N_EDGES + N_NODES)  // 650000
#define N_SEG   (R_AUG * N_NODES)      // 1010000
#define N_BATCH 65536

// persistent layer config
#define TM      128
#define NTILES  ((N_NODES + TM - 1) / TM)          // 79
#define NITEMS  (NTILES * R_AUG)                   // 7979
#define NCTA    148
#define WPC     ((NITEMS + NCTA - 1) / NCTA)       // 54
#define NSLAB   3
#define SEG_CHUNK ((N_SEG + NCTA - 1) / NCTA)      // 6825

// fp16 tile row stride: 128 + 8 pad = 136 halves = 272 bytes (17 * 16B)
#define TS      272
#define PLANE   34816                               // 128 * 272

// smem layout (bytes)
#define OFF_AH   0                                  // A hi [128][136]
#define OFF_AL   PLANE                              // A lo
#define OFF_B0   (2*PLANE)                          // B buf 0: hi|lo  (2*PLANE)
#define OFF_B1   (4*PLANE)                          // B buf 1: hi|lo
#define SMEM_TOT (6*PLANE + 64)                     // ~204.1 KB

typedef unsigned long long u64;
typedef unsigned int u32;
typedef unsigned short u16;

// ---------------- static device scratch ----------------
__device__ int   g_deg[N_SEG];
__device__ int   g_rowptr[N_SEG + 1];
__device__ int   g_cursor[N_SEG];
__device__ int   g_ctasum[NCTA];
__device__ int   g_csr[E_AUG];                         // src only
__device__ u16   g_Bt1[(size_t)R_AUG * 32768];         // layer1 W: fp16 hi[128][128] | lo[128][128], row=n col=k
__device__ u16   g_Bt2[(size_t)R_AUG * 32768];         // layer2 W
__device__ float g_h1[N_NODES * D];
__device__ float g_h2[N_NODES * D];
__device__ float g_partial[(size_t)NSLAB * N_NODES * D];
__device__ unsigned g_bcnt[8];                         // grid barrier counters (self-reset)
__device__ unsigned g_brel[8];                         // grid barrier release epochs (monotonic)

// ---------------- small helpers ----------------
__device__ __forceinline__ u32 smem_u32(const void* p) {
    u32 a;
    asm("{ .reg .u64 t; cvta.to.shared.u64 t, %1; cvt.u32.u64 %0, t; }" : "=r"(a) : "l"(p));
    return a;
}
__device__ __forceinline__ u16 f2h(float v) {
    u16 r; asm("cvt.rn.f16.f32 %0, %1;" : "=h"(r) : "f"(v)); return r;
}
__device__ __forceinline__ float h2f(u16 v) {
    float r; asm("cvt.f32.f16 %0, %1;" : "=f"(r) : "h"(v)); return r;
}

#define LDSM4(r, addr)                                                          \
    asm volatile("ldmatrix.sync.aligned.m8n8.x4.shared.b16 {%0,%1,%2,%3}, [%4];"\
        : "=r"((r)[0]), "=r"((r)[1]), "=r"((r)[2]), "=r"((r)[3]) : "r"(addr))

#define MMA16816(c, a, b0_, b1_)                                                \
    asm volatile("mma.sync.aligned.m16n8k16.row.col.f32.f16.f16.f32 "           \
        "{%0,%1,%2,%3}, {%4,%5,%6,%7}, {%8,%9}, {%0,%1,%2,%3};"                 \
        : "+f"((c)[0]), "+f"((c)[1]), "+f"((c)[2]), "+f"((c)[3])                \
        : "r"((a)[0]), "r"((a)[1]), "r"((a)[2]), "r"((a)[3]), "r"(b0_), "r"(b1_))

#define CP_ASYNC16(dst, src)                                                    \
    asm volatile("cp.async.cg.shared.global [%0], [%1], 16;" :: "r"(dst), "l"(src))
#define CP_COMMIT() asm volatile("cp.async.commit_group;" ::: "memory")
#define CP_WAIT0()  asm volatile("cp.async.wait_group 0;" ::: "memory")

// ---- replay-safe software grid barrier (all NCTA CTAs co-resident) ----
__device__ __forceinline__ void grid_bar(int slot) {
    __threadfence();
    __syncthreads();
    if (threadIdx.x == 0) {
        volatile unsigned* rel = (volatile unsigned*)&g_brel[slot];
        unsigned e0 = *rel;
        unsigned t = atomicAdd(&g_bcnt[slot], 1u);
        if (t == NCTA - 1) {
            g_bcnt[slot] = 0;
            __threadfence();
            atomicAdd(&g_brel[slot], 1u);
        } else {
            while (*rel == e0) { }
        }
        __threadfence();
    }
    __syncthreads();
}

// ---- block exclusive scan over 256 ints; returns exclusive, sets total ----
__device__ __forceinline__ int block_excl_scan(int v, int* ssc, int& total) {
    int lane = threadIdx.x & 31, w = threadIdx.x >> 5;
    int x = v;
    #pragma unroll
    for (int o = 1; o < 32; o <<= 1) {
        int y = __shfl_up_sync(0xffffffffu, x, o);
        if (lane >= o) x += y;
    }
    if (lane == 31) ssc[w] = x;
    __syncthreads();
    if (w == 0) {
        int tval = (lane < 8) ? ssc[lane] : 0;
        #pragma unroll
        for (int o = 1; o < 8; o <<= 1) {
            int y = __shfl_up_sync(0xffffffffu, tval, o);
            if (lane >= o) tval += y;
        }
        if (lane < 8) ssc[lane] = tval;    // inclusive warp totals
    }
    __syncthreads();
    int wbase = (w > 0) ? ssc[w - 1] : 0;
    total = ssc[7];
    __syncthreads();
    return wbase + x - v;
}

__device__ __forceinline__ void aug_edge(const int* __restrict__ g, int e,
                                         int& seg, int& src) {
    if (e < N_EDGES) {
        int s = g[e*3+0], p = g[e*3+1], o = g[e*3+2];
        seg = p * N_NODES + o;  src = s;
    } else if (e < 2*N_EDGES) {
        int e2 = e - N_EDGES;
        int s = g[e2*3+0], p = g[e2*3+1], o = g[e2*3+2];
        seg = (p + N_RELS) * N_NODES + s;  src = o;
    } else {
        int i = e - 2*N_EDGES;
        seg = 2*N_RELS*N_NODES + i;  src = i;
    }
}

// ---------------- W -> fp16 hi/lo B^T planes (row=n, col=k) ----------------
__global__ void convert_w_kernel(const float* __restrict__ W, u16* __restrict__ Bt) {
    int r = blockIdx.x;
    const float* Wr = W + (size_t)r * (D * D);
    u16* B = Bt + (size_t)r * 32768;
    for (int idx = threadIdx.x; idx < D * D; idx += blockDim.x) {
        int k = idx >> 7, n = idx & 127;
        float v = Wr[k * D + n];
        u16 h = f2h(v);
        u16 l = f2h(v - h2f(h));
        B[n * D + k]         = h;
        B[16384 + n * D + k] = l;
    }
}

__global__ void zero_partial_kernel() {
    int i = blockIdx.x * blockDim.x + threadIdx.x;
    const int n4 = NSLAB * N_NODES * D / 4;
    if (i < n4) ((float4*)g_partial)[i] = make_float4(0.f, 0.f, 0.f, 0.f);
}

// ---------------- flush register accumulators to a partial slab ----------------
__device__ __forceinline__ void flush_acc(float acc[2][8][4], int cur_t,
                                          int warp, int lane) {
    int slab_i = blockIdx.x - (cur_t * R_AUG) / WPC;
    float* slab = g_partial + (size_t)slab_i * (N_NODES * D);
    int wm = warp & 3, wn = warp >> 2;
    int r0 = cur_t * TM + wm * 32 + (lane >> 2);
    int cb = wn * 64 + (lane & 3) * 2;
    #pragma unroll
    for (int mf = 0; mf < 2; mf++) {
        int rowA = r0 + mf * 16;
        int rowB = rowA + 8;
        #pragma unroll
        for (int nf = 0; nf < 8; nf++) {
            int col = cb + nf * 8;
            if (rowA < N_NODES)
                *(float2*)(slab + (size_t)rowA * D + col) =
                    make_float2(acc[mf][nf][0], acc[mf][nf][1]);
            if (rowB < N_NODES)
                *(float2*)(slab + (size_t)rowB * D + col) =
                    make_float2(acc[mf][nf][2], acc[mf][nf][3]);
        }
    }
}

// ---- issue cp.async prefetch of one relation's B tiles into an smem buffer ----
__device__ __forceinline__ void prefetch_B(u32 smbuf, const u16* __restrict__ Bt, int r) {
    const char* src_base = (const char*)(Bt + (size_t)r * 32768);
    int tid = threadIdx.x;
    #pragma unroll
    for (int q = 0; q < 16; q++) {
        int idx = tid + q * 256;           // 0..4095 16B chunks (hi then lo)
        int plane = idx >> 11;
        int i2 = idx & 2047;
        int row = i2 >> 4, c16 = i2 & 15;
        u32 dst = smbuf + plane * PLANE + row * TS + c16 * 16;
        const char* src = src_base + ((size_t)plane * 16384 + row * 128 + c16 * 8) * 2;
        CP_ASYNC16(dst, src);
    }
}

// ---------------- persistent mega kernel: (optional CSR build) + layer ----------------
extern "C" __global__ void __launch_bounds__(256, 1)
layer_mega_kernel(const float* __restrict__ x, const int* __restrict__ graph,
                  const u16* __restrict__ Bt, int build_csr) {
    extern __shared__ char smem[];
    __shared__ int ssc[16];
    __shared__ int sbase;
    u32 smb = smem_u32(smem);

    int tid  = threadIdx.x;
    int bid  = blockIdx.x;
    int gtid = bid * 256 + tid;
    const int gstride = NCTA * 256;

    // ================= CSR build (layer-1 instance only) =================
    if (build_csr) {
        // P0: zero degrees
        for (int i = gtid; i < N_SEG; i += gstride) g_deg[i] = 0;
        grid_bar(0);
        // P1: histogram
        for (int e = gtid; e < E_AUG; e += gstride) {
            int seg, src;
            aug_edge(graph, e, seg, src);
            atomicAdd(&g_deg[seg], 1);
        }
        grid_bar(1);
        // P2: per-CTA degree sum over contiguous chunk
        int s0 = bid * SEG_CHUNK;
        int s1 = min(s0 + SEG_CHUNK, N_SEG);
        {
            int lsum = 0;
            for (int i = s0 + tid; i < s1; i += 256) lsum += g_deg[i];
            // block reduce
            #pragma unroll
            for (int o = 16; o; o >>= 1) lsum += __shfl_xor_sync(0xffffffffu, lsum, o);
            if ((tid & 31) == 0) ssc[tid >> 5] = lsum;
            __syncthreads();
            if (tid < 8) {
                int v = ssc[tid];
                #pragma unroll
                for (int o = 4; o; o >>= 1) v += __shfl_xor_sync(0xffu, v, o);
                if (tid == 0) g_ctasum[bid] = v;
            }
            __syncthreads();
        }
        grid_bar(2);
        // P3: CTA base via block scan of the 148 CTA sums, then local prefix walk
        {
            int v = (tid < NCTA) ? g_ctasum[tid] : 0;
            int tot;
            int ex = block_excl_scan(v, ssc, tot);
            if (tid == bid) sbase = ex;
            __syncthreads();
            int run = sbase;
            const int nchunk = (SEG_CHUNK + 255) / 256;
            for (int c = 0; c < nchunk; c++) {
                int gi = s0 + c * 256 + tid;
                int dv = (gi < s1) ? g_deg[gi] : 0;
                int ctot;
                int cex = block_excl_scan(dv, ssc, ctot);
                if (gi < s1) {
                    int rp = run + cex;
                    g_rowptr[gi] = rp;
                    g_cursor[gi] = rp;
                }
                run += ctot;
            }
            if (bid == NCTA - 1 && tid == 0) g_rowptr[N_SEG] = E_AUG;
        }
        grid_bar(3);
        // P4: scatter
        for (int e = gtid; e < E_AUG; e += gstride) {
            int seg, src;
            aug_edge(graph, e, seg, src);
            int pos = atomicAdd(&g_cursor[seg], 1);
            g_csr[pos] = src;
        }
        grid_bar(4);
    }

    // ================= layer items =================
    int warp = tid >> 5, lane = tid & 31;
    int wm = warp & 3, wn = warp >> 2;

    // ldmatrix per-lane row offsets (bytes) within a tile
    u32 rowa = (u32)(wm * 32 + (lane & 15)) * TS + (u32)((lane >> 4) << 3) * 2;
    u32 rowb = (u32)(wn * 64 + ((lane >> 4) << 3) + (lane & 7)) * TS
             + (u32)(((lane >> 3) & 1) << 3) * 2;
    u32 aHb = smb + OFF_AH + rowa, aLb = smb + OFF_AL + rowa;

    int bsub = tid & 3;            // 32-dim chunk
    int brow_lo = tid >> 2;        // rows 0..63 (pass 0) / +64 (pass 1)

    float acc[2][8][4];
    #pragma unroll
    for (int i = 0; i < 2; i++)
        #pragma unroll
        for (int j = 0; j < 8; j++)
            #pragma unroll
            for (int q = 0; q < 4; q++) acc[i][j][q] = 0.f;

    int i0 = bid * WPC;
    int i1 = min(i0 + WPC, NITEMS);
    if (i0 >= i1) return;

    int cur_t = -1;

    // prefetch first item's B
    {
        int t0 = i0 / R_AUG, r0 = i0 - t0 * R_AUG;
        prefetch_B(smb + ((i0 & 1) ? OFF_B1 : OFF_B0), Bt, r0);
        CP_COMMIT();
    }

    for (int it = i0; it < i1; ++it) {
        int t = it / R_AUG, r = it - t * R_AUG;
        (void)r;
        int tb = t * TM;
        int nrows = min(TM, N_NODES - tb);
        int segbase = (it - t * R_AUG) * N_NODES + tb;   // r * N_NODES + tb

        if (t != cur_t) {
            if (cur_t >= 0) {
                flush_acc(acc, cur_t, warp, lane);
                #pragma unroll
                for (int i = 0; i < 2; i++)
                    #pragma unroll
                    for (int j = 0; j < 8; j++)
                        #pragma unroll
                        for (int q = 0; q < 4; q++) acc[i][j][q] = 0.f;
            }
            cur_t = t;
        }

        __syncthreads();   // previous GEMM done reading A tiles

        // ---- (A) build + convert A tiles, register-resident, no atomics ----
        #pragma unroll
        for (int p = 0; p < 2; p++) {
            int row = brow_lo + p * 64;
            float4 a[8];
            #pragma unroll
            for (int q = 0; q < 8; q++) a[q] = make_float4(0.f, 0.f, 0.f, 0.f);
            int deg = 0;
            if (row < nrows) {
                int seg = segbase + row;
                int s = g_rowptr[seg], e = g_rowptr[seg + 1];
                deg = e - s;
                for (int j = s; j < e; ++j) {
                    int src = g_csr[j];
                    const float4* v = (const float4*)(x + (size_t)src * D + (bsub << 5));
                    #pragma unroll
                    for (int q = 0; q < 8; q++) {
                        float4 w = v[q];
                        a[q].x += w.x; a[q].y += w.y; a[q].z += w.z; a[q].w += w.w;
                    }
                }
            }
            float nrm = 1.0f / fmaxf((float)deg, 1.0f);
            u32* AH = (u32*)(smem + OFF_AH + row * TS + (bsub << 6));
            u32* AL = (u32*)(smem + OFF_AL + row * TS + (bsub << 6));
            #pragma unroll
            for (int q = 0; q < 8; q++) {
                float v0 = a[q].x * nrm, v1 = a[q].y * nrm;
                float v2 = a[q].z * nrm, v3 = a[q].w * nrm;
                u16 h0 = f2h(v0), h1 = f2h(v1), h2 = f2h(v2), h3 = f2h(v3);
                u16 l0 = f2h(v0 - h2f(h0)), l1 = f2h(v1 - h2f(h1));
                u16 l2 = f2h(v2 - h2f(h2)), l3 = f2h(v3 - h2f(h3));
                AH[q*2+0] = (u32)h0 | ((u32)h1 << 16);
                AH[q*2+1] = (u32)h2 | ((u32)h3 << 16);
                AL[q*2+0] = (u32)l0 | ((u32)l1 << 16);
                AL[q*2+1] = (u32)l2 | ((u32)l3 << 16);
            }
        }

        // ---- (B) wait for this item's B; kick off prefetch of next ----
        CP_WAIT0();
        __syncthreads();
        if (it + 1 < i1) {
            int t2 = (it + 1) / R_AUG, r2 = (it + 1) - t2 * R_AUG;
            prefetch_B(smb + (((it + 1) & 1) ? OFF_B1 : OFF_B0), Bt, r2);
            CP_COMMIT();
        }

        u32 bbase = smb + ((it & 1) ? OFF_B1 : OFF_B0);
        u32 bHb = bbase + rowb;
        u32 bLb = bbase + PLANE + rowb;

        // ---- (C) 128x128x128 GEMM, 3-term fp16 split on HMMA ----
        #pragma unroll
        for (int ks = 0; ks < 8; ks++) {
            u32 k2 = (u32)ks * 32;                  // k0 * 2 bytes
            u32 aH0[4], aH1[4], aL0[4], aL1[4];
            LDSM4(aH0, aHb + k2);
            LDSM4(aH1, aHb + 16 * TS + k2);
            LDSM4(aL0, aLb + k2);
            LDSM4(aL1, aLb + 16 * TS + k2);
            #pragma unroll
            for (int nf2 = 0; nf2 < 4; nf2++) {
                u32 bH[4], bL[4];
                LDSM4(bH, bHb + (u32)nf2 * 16 * TS + k2);
                LDSM4(bL, bLb + (u32)nf2 * 16 * TS + k2);
                int n0 = nf2 * 2, n1 = nf2 * 2 + 1;
                MMA16816(acc[0][n0], aH0, bH[0], bH[1]);
                MMA16816(acc[0][n0], aL0, bH[0], bH[1]);
                MMA16816(acc[0][n0], aH0, bL[0], bL[1]);
                MMA16816(acc[1][n0], aH1, bH[0], bH[1]);
                MMA16816(acc[1][n0], aL1, bH[0], bH[1]);
                MMA16816(acc[1][n0], aH1, bL[0], bL[1]);
                MMA16816(acc[0][n1], aH0, bH[2], bH[3]);
                MMA16816(acc[0][n1], aL0, bH[2], bH[3]);
                MMA16816(acc[0][n1], aH0, bL[2], bL[3]);
                MMA16816(acc[1][n1], aH1, bH[2], bH[3]);
                MMA16816(acc[1][n1], aL1, bH[2], bH[3]);
                MMA16816(acc[1][n1], aH1, bL[2], bL[3]);
            }
        }
    }

    if (cur_t >= 0) flush_acc(acc, cur_t, warp, lane);
}

// ---------------- reduce slabs + bias (+relu) ----------------
__global__ void reduce_kernel(const float* __restrict__ bias,
                              float* __restrict__ out, int do_relu) {
    int i = blockIdx.x * blockDim.x + threadIdx.x;
    const int n4 = N_NODES * D / 4;
    if (i >= n4) return;
    const float4* p4 = (const float4*)g_partial;
    float4 s = p4[i];
    #pragma unroll
    for (int k = 1; k < NSLAB; k++) {
        float4 t = p4[i + (size_t)k * n4];
        s.x += t.x; s.y += t.y; s.z += t.z; s.w += t.w;
    }
    float4 b = ((const float4*)bias)[i & 31];
    s.x += b.x; s.y += b.y; s.z += b.z; s.w += b.w;
    if (do_relu) {
        s.x = fmaxf(s.x, 0.f); s.y = fmaxf(s.y, 0.f);
        s.z = fmaxf(s.z, 0.f); s.w = fmaxf(s.w, 0.f);
    }
    ((float4*)out)[i] = s;
}

// ---------------- scoring: warp per batch item ----------------
__global__ void score_kernel(const int* __restrict__ batch,
                             const float* __restrict__ xn,
                             const float* __restrict__ rels,
                             float* __restrict__ out) {
    int w = (blockIdx.x * blockDim.x + threadIdx.x) >> 5;
    int lane = threadIdx.x & 31;
    if (w >= N_BATCH) return;
    int bs = batch[w*3+0], bp = batch[w*3+1], bo = batch[w*3+2];
    float4 a = ((const float4*)(xn + (size_t)bs * D))[lane];
    float4 r = ((const float4*)(rels + (size_t)bp * D))[lane];
    float4 c = ((const float4*)(xn + (size_t)bo * D))[lane];
    float s = a.x*r.x*c.x + a.y*r.y*c.y + a.z*r.z*c.z + a.w*r.w*c.w;
    #pragma unroll
    for (int o = 16; o; o >>= 1) s += __shfl_xor_sync(0xffffffffu, s, o);
    if (lane == 0) out[w] = s;
}

// ---------------- launch ----------------
extern "C" void kernel_launch(void* const* d_in, const int* in_sizes, int n_in,
                              void* d_out, int out_size) {
    const int*   graph = (const int*)d_in[0];
    const int*   batch = (const int*)d_in[1];
    const float* x0    = (const float*)d_in[2];
    const float* W1    = (const float*)d_in[3];
    const float* b1    = (const float*)d_in[4];
    const float* W2    = (const float*)d_in[5];
    const float* b2    = (const float*)d_in[6];
    const float* rels  = (const float*)d_in[7];
    float* out = (float*)d_out;

    void *p_h1 = nullptr, *p_h2 = nullptr, *p_bt1 = nullptr, *p_bt2 = nullptr;
    cudaGetSymbolAddress(&p_h1, g_h1);
    cudaGetSymbolAddress(&p_h2, g_h2);
    cudaGetSymbolAddress(&p_bt1, g_Bt1);
    cudaGetSymbolAddress(&p_bt2, g_Bt2);
    float* h1 = (float*)p_h1;
    float* h2 = (float*)p_h2;
    u16* bt1 = (u16*)p_bt1;
    u16* bt2 = (u16*)p_bt2;

    cudaFuncSetAttribute(layer_mega_kernel,
                         cudaFuncAttributeMaxDynamicSharedMemorySize, SMEM_TOT);

    const int zp_grid = (NSLAB * N_NODES * D / 4 + 255) / 256;
    const int rd_grid = (N_NODES * D / 4 + 255) / 256;

    // launches 1-3: W conversions + partial zero (layer kernel lands in slot 4)
    convert_w_kernel<<<R_AUG, 256>>>(W1, bt1);
    convert_w_kernel<<<R_AUG, 256>>>(W2, bt2);
    zero_partial_kernel<<<zp_grid, 256>>>();

    // layer 1 (builds CSR internally via grid barriers)
    layer_mega_kernel<<<NCTA, 256, SMEM_TOT>>>(x0, graph, bt1, 1);
    reduce_kernel<<<rd_grid, 256>>>(b1, h1, 1);

    // layer 2
    zero_partial_kernel<<<zp_grid, 256>>>();
    layer_mega_kernel<<<NCTA, 256, SMEM_TOT>>>(h1, graph, bt2, 0);
    reduce_kernel<<<rd_grid, 256>>>(b2, h2, 0);

    // scoring
    score_kernel<<<(N_BATCH * 32) / 256, 256>>>(batch, h2, rels, out);
}

// round 9
// speedup vs baseline: 1.1382x; 1.1382x over previous
#include <cuda_runtime.h>
#include <cuda_fp16.h>

// ---------------- problem constants ----------------
#define N_NODES 10000
#define N_RELS  50
#define R_AUG   101                    // 2*N_RELS + 1
#define D       128
#define N_EDGES 320000
#define E_AUG   (2*N_EDGES + N_NODES)  // 650000
#define N_SEG   (R_AUG * N_NODES)      // 1010000
#define N_BATCH 65536

// persistent layer config: 2 CTAs/SM, M-tile 64
#define TM      64
#define NTILES  ((N_NODES + TM - 1) / TM)          // 157
#define NITEMS  (NTILES * R_AUG)                   // 15857
#define NCTA    296
#define WPC     ((NITEMS + NCTA - 1) / NCTA)       // 54
#define NSLAB   3
#define SEG_CHUNK ((N_SEG + NCTA - 1) / NCTA)      // 3413

// fp16 tile row stride: 128 + 8 pad = 136 halves = 272 bytes
#define TS      272
#define APLANE  (64 * TS)                           // 17408
#define BPLANE  (128 * TS)                          // 34816

// smem layout (bytes)
#define OFF_AH   0                                  // A hi [64][136]
#define OFF_AL   APLANE                             // A lo
#define OFF_B    (2*APLANE)                         // B hi [128][136], lo at +BPLANE
#define SMEM_TOT (2*APLANE + 2*BPLANE + 64)         // ~104.5 KB

typedef unsigned long long u64;
typedef unsigned int u32;
typedef unsigned short u16;

// ---------------- static device scratch ----------------
__device__ int   g_deg[N_SEG];
__device__ int   g_rowptr[N_SEG + 1];
__device__ int   g_cursor[N_SEG];
__device__ int   g_ctasum[NCTA];
__device__ int   g_csr[E_AUG];                         // src only
__device__ u16   g_Bt1[(size_t)R_AUG * 32768];         // layer1 W: fp16 hi[128][128] | lo, row=n col=k
__device__ u16   g_Bt2[(size_t)R_AUG * 32768];         // layer2 W
__device__ float g_h1[N_NODES * D];
__device__ float g_h2[N_NODES * D];
__device__ float g_partial[(size_t)NSLAB * N_NODES * D];
__device__ unsigned g_bcnt[8];                         // grid barrier counters (self-reset)
__device__ unsigned g_brel[8];                         // grid barrier release epochs (monotonic)

// ---------------- small helpers ----------------
__device__ __forceinline__ u32 smem_u32(const void* p) {
    u32 a;
    asm("{ .reg .u64 t; cvta.to.shared.u64 t, %1; cvt.u32.u64 %0, t; }" : "=r"(a) : "l"(p));
    return a;
}
__device__ __forceinline__ u16 f2h(float v) {
    u16 r; asm("cvt.rn.f16.f32 %0, %1;" : "=h"(r) : "f"(v)); return r;
}
__device__ __forceinline__ float h2f(u16 v) {
    float r; asm("cvt.f32.f16 %0, %1;" : "=f"(r) : "h"(v)); return r;
}

#define LDSM4(r, addr)                                                          \
    asm volatile("ldmatrix.sync.aligned.m8n8.x4.shared.b16 {%0,%1,%2,%3}, [%4];"\
        : "=r"((r)[0]), "=r"((r)[1]), "=r"((r)[2]), "=r"((r)[3]) : "r"(addr))

#define MMA16816(c, a, b0_, b1_)                                                \
    asm volatile("mma.sync.aligned.m16n8k16.row.col.f32.f16.f16.f32 "           \
        "{%0,%1,%2,%3}, {%4,%5,%6,%7}, {%8,%9}, {%0,%1,%2,%3};"                 \
        : "+f"((c)[0]), "+f"((c)[1]), "+f"((c)[2]), "+f"((c)[3])                \
        : "r"((a)[0]), "r"((a)[1]), "r"((a)[2]), "r"((a)[3]), "r"(b0_), "r"(b1_))

#define CP_ASYNC16(dst, src)                                                    \
    asm volatile("cp.async.cg.shared.global [%0], [%1], 16;" :: "r"(dst), "l"(src))
#define CP_COMMIT() asm volatile("cp.async.commit_group;" ::: "memory")
#define CP_WAIT0()  asm volatile("cp.async.wait_group 0;" ::: "memory")

// ---- replay-safe software grid barrier (all NCTA CTAs co-resident: 2/SM) ----
__device__ __forceinline__ void grid_bar(int slot) {
    __threadfence();
    __syncthreads();
    if (threadIdx.x == 0) {
        volatile unsigned* rel = (volatile unsigned*)&g_brel[slot];
        unsigned e0 = *rel;
        unsigned t = atomicAdd(&g_bcnt[slot], 1u);
        if (t == NCTA - 1) {
            g_bcnt[slot] = 0;
            __threadfence();
            atomicAdd(&g_brel[slot], 1u);
        } else {
            while (*rel == e0) { }
        }
        __threadfence();
    }
    __syncthreads();
}

// ---- block exclusive scan over 256 ints; returns exclusive, sets total ----
__device__ __forceinline__ int block_excl_scan(int v, int* ssc, int& total) {
    int lane = threadIdx.x & 31, w = threadIdx.x >> 5;
    int x = v;
    #pragma unroll
    for (int o = 1; o < 32; o <<= 1) {
        int y = __shfl_up_sync(0xffffffffu, x, o);
        if (lane >= o) x += y;
    }
    if (lane == 31) ssc[w] = x;
    __syncthreads();
    if (w == 0) {
        int tval = (lane < 8) ? ssc[lane] : 0;
        #pragma unroll
        for (int o = 1; o < 8; o <<= 1) {
            int y = __shfl_up_sync(0xffffffffu, tval, o);
            if (lane >= o) tval += y;
        }
        if (lane < 8) ssc[lane] = tval;    // inclusive warp totals
    }
    __syncthreads();
    int wbase = (w > 0) ? ssc[w - 1] : 0;
    total = ssc[7];
    __syncthreads();
    return wbase + x - v;
}

__device__ __forceinline__ void aug_edge(const int* __restrict__ g, int e,
                                         int& seg, int& src) {
    if (e < N_EDGES) {
        int s = g[e*3+0], p = g[e*3+1], o = g[e*3+2];
        seg = p * N_NODES + o;  src = s;
    } else if (e < 2*N_EDGES) {
        int e2 = e - N_EDGES;
        int s = g[e2*3+0], p = g[e2*3+1], o = g[e2*3+2];
        seg = (p + N_RELS) * N_NODES + s;  src = o;
    } else {
        int i = e - 2*N_EDGES;
        seg = 2*N_RELS*N_NODES + i;  src = i;
    }
}

// ---------------- W -> fp16 hi/lo B^T planes (row=n, col=k) ----------------
__global__ void convert_w_kernel(const float* __restrict__ W, u16* __restrict__ Bt) {
    int r = blockIdx.x;
    const float* Wr = W + (size_t)r * (D * D);
    u16* B = Bt + (size_t)r * 32768;
    for (int idx = threadIdx.x; idx < D * D; idx += blockDim.x) {
        int k = idx >> 7, n = idx & 127;
        float v = Wr[k * D + n];
        u16 h = f2h(v);
        u16 l = f2h(v - h2f(h));
        B[n * D + k]         = h;
        B[16384 + n * D + k] = l;
    }
}

__global__ void zero_partial_kernel() {
    int i = blockIdx.x * blockDim.x + threadIdx.x;
    const int n4 = NSLAB * N_NODES * D / 4;
    if (i < n4) ((float4*)g_partial)[i] = make_float4(0.f, 0.f, 0.f, 0.f);
}

// ---------------- flush register accumulators to a partial slab ----------------
__device__ __forceinline__ void flush_acc(float acc[2][4][4], int cur_t,
                                          int warp, int lane) {
    int slab_i = blockIdx.x - (cur_t * R_AUG) / WPC;
    float* slab = g_partial + (size_t)slab_i * (N_NODES * D);
    int wm = warp & 1, wn = warp >> 1;
    int r0 = cur_t * TM + wm * 32 + (lane >> 2);
    int cb = wn * 32 + (lane & 3) * 2;
    #pragma unroll
    for (int mf = 0; mf < 2; mf++) {
        int rowA = r0 + mf * 16;
        int rowB = rowA + 8;
        #pragma unroll
        for (int nf = 0; nf < 4; nf++) {
            int col = cb + nf * 8;
            if (rowA < N_NODES)
                *(float2*)(slab + (size_t)rowA * D + col) =
                    make_float2(acc[mf][nf][0], acc[mf][nf][1]);
            if (rowB < N_NODES)
                *(float2*)(slab + (size_t)rowB * D + col) =
                    make_float2(acc[mf][nf][2], acc[mf][nf][3]);
        }
    }
}

// ---- cp.async prefetch of one relation's B hi/lo tiles (single buffer) ----
__device__ __forceinline__ void prefetch_B(u32 smbuf, const u16* __restrict__ Bt, int r) {
    const char* src_base = (const char*)(Bt + (size_t)r * 32768);
    int tid = threadIdx.x;
    #pragma unroll
    for (int q = 0; q < 16; q++) {
        int idx = tid + q * 256;           // 0..4095 16B chunks (hi then lo)
        int plane = idx >> 11;
        int i2 = idx & 2047;
        int row = i2 >> 4, c16 = i2 & 15;
        u32 dst = smbuf + plane * BPLANE + row * TS + c16 * 16;
        const char* src = src_base + (size_t)plane * 32768 + row * 256 + c16 * 16;
        CP_ASYNC16(dst, src);
    }
}

// ---------------- persistent mega kernel: (optional CSR build) + layer ----------------
extern "C" __global__ void __launch_bounds__(256, 2)
layer_mega_kernel(const float* __restrict__ x, const int* __restrict__ graph,
                  const u16* __restrict__ Bt, int build_csr) {
    extern __shared__ char smem[];
    __shared__ int ssc[16];
    __shared__ int sbase;
    u32 smb = smem_u32(smem);

    int tid  = threadIdx.x;
    int bid  = blockIdx.x;
    int gtid = bid * 256 + tid;
    const int gstride = NCTA * 256;

    // ================= CSR build (layer-1 instance only) =================
    if (build_csr) {
        // P0: zero degrees
        for (int i = gtid; i < N_SEG; i += gstride) g_deg[i] = 0;
        grid_bar(0);
        // P1: histogram
        for (int e = gtid; e < E_AUG; e += gstride) {
            int seg, src;
            aug_edge(graph, e, seg, src);
            atomicAdd(&g_deg[seg], 1);
        }
        grid_bar(1);
        // P2: per-CTA degree sum over contiguous chunk
        int s0 = bid * SEG_CHUNK;
        int s1 = min(s0 + SEG_CHUNK, N_SEG);
        {
            int lsum = 0;
            for (int i = s0 + tid; i < s1; i += 256) lsum += g_deg[i];
            #pragma unroll
            for (int o = 16; o; o >>= 1) lsum += __shfl_xor_sync(0xffffffffu, lsum, o);
            if ((tid & 31) == 0) ssc[tid >> 5] = lsum;
            __syncthreads();
            if (tid < 8) {
                int v = ssc[tid];
                #pragma unroll
                for (int o = 4; o; o >>= 1) v += __shfl_xor_sync(0xffu, v, o);
                if (tid == 0) g_ctasum[bid] = v;
            }
            __syncthreads();
        }
        grid_bar(2);
        // P3: CTA base via pairwise block scan of 296 CTA sums, then local walk
        {
            int va = 0, vp = 0;
            if (tid < NCTA / 2) {
                va = g_ctasum[2 * tid];
                vp = va + g_ctasum[2 * tid + 1];
            }
            int tot;
            int ex = block_excl_scan(vp, ssc, tot);
            if (2 * tid == bid) sbase = ex;
            if (2 * tid + 1 == bid) sbase = ex + va;
            __syncthreads();
            int run = sbase;
            const int nchunk = (SEG_CHUNK + 255) / 256;
            for (int c = 0; c < nchunk; c++) {
                int gi = s0 + c * 256 + tid;
                int dv = (gi < s1) ? g_deg[gi] : 0;
                int ctot;
                int cex = block_excl_scan(dv, ssc, ctot);
                if (gi < s1) {
                    int rp = run + cex;
                    g_rowptr[gi] = rp;
                    g_cursor[gi] = rp;
                }
                run += ctot;
            }
            if (bid == NCTA - 1 && tid == 0) g_rowptr[N_SEG] = E_AUG;
        }
        grid_bar(3);
        // P4: scatter
        for (int e = gtid; e < E_AUG; e += gstride) {
            int seg, src;
            aug_edge(graph, e, seg, src);
            int pos = atomicAdd(&g_cursor[seg], 1);
            g_csr[pos] = src;
        }
        grid_bar(4);
    }

    // ================= layer items =================
    int warp = tid >> 5, lane = tid & 31;
    int wm = warp & 1, wn = warp >> 1;

    // ldmatrix per-lane row offsets (bytes) within a tile
    u32 rowa = (u32)(wm * 32 + (lane & 15)) * TS + (u32)((lane >> 4) << 3) * 2;
    u32 rowb = (u32)(wn * 32 + ((lane >> 4) << 3) + (lane & 7)) * TS
             + (u32)(((lane >> 3) & 1) << 3) * 2;
    u32 aHb = smb + OFF_AH + rowa, aLb = smb + OFF_AL + rowa;
    u32 bHb = smb + OFF_B + rowb, bLb = smb + OFF_B + BPLANE + rowb;

    int bsub = tid & 3;            // 32-dim chunk
    int brow = tid >> 2;           // row 0..63

    float acc[2][4][4];
    #pragma unroll
    for (int i = 0; i < 2; i++)
        #pragma unroll
        for (int j = 0; j < 4; j++)
            #pragma unroll
            for (int q = 0; q < 4; q++) acc[i][j][q] = 0.f;

    int i0 = bid * WPC;
    int i1 = min(i0 + WPC, NITEMS);
    if (i0 >= i1) return;

    int cur_t = -1;

    for (int it = i0; it < i1; ++it) {
        int t = it / R_AUG;
        int r = it - t * R_AUG;
        int tb = t * TM;
        int nrows = min(TM, N_NODES - tb);
        int segbase = r * N_NODES + tb;

        if (t != cur_t) {
            if (cur_t >= 0) {
                flush_acc(acc, cur_t, warp, lane);
                #pragma unroll
                for (int i = 0; i < 2; i++)
                    #pragma unroll
                    for (int j = 0; j < 4; j++)
                        #pragma unroll
                        for (int q = 0; q < 4; q++) acc[i][j][q] = 0.f;
            }
            cur_t = t;
        }

        __syncthreads();   // previous GEMM done reading A & B tiles

        // ---- (A) kick B prefetch (buffer free now), overlaps the build ----
        prefetch_B(smb + OFF_B, Bt, r);
        CP_COMMIT();

        // ---- (B) build + convert A tiles, register-resident, no atomics ----
        {
            float4 a[8];
            #pragma unroll
            for (int q = 0; q < 8; q++) a[q] = make_float4(0.f, 0.f, 0.f, 0.f);
            int deg = 0;
            if (brow < nrows) {
                int seg = segbase + brow;
                int s = g_rowptr[seg], e = g_rowptr[seg + 1];
                deg = e - s;
                for (int j = s; j < e; ++j) {
                    int src = g_csr[j];
                    const float4* v = (const float4*)(x + (size_t)src * D + (bsub << 5));
                    #pragma unroll
                    for (int q = 0; q < 8; q++) {
                        float4 w = v[q];
                        a[q].x += w.x; a[q].y += w.y; a[q].z += w.z; a[q].w += w.w;
                    }
                }
            }
            float nrm = 1.0f / fmaxf((float)deg, 1.0f);
            u32* AH = (u32*)(smem + OFF_AH + brow * TS + (bsub << 6));
            u32* AL = (u32*)(smem + OFF_AL + brow * TS + (bsub << 6));
            #pragma unroll
            for (int q = 0; q < 8; q++) {
                float v0 = a[q].x * nrm, v1 = a[q].y * nrm;
                float v2 = a[q].z * nrm, v3 = a[q].w * nrm;
                u16 h0 = f2h(v0), h1 = f2h(v1), h2 = f2h(v2), h3 = f2h(v3);
                u16 l0 = f2h(v0 - h2f(h0)), l1 = f2h(v1 - h2f(h1));
                u16 l2 = f2h(v2 - h2f(h2)), l3 = f2h(v3 - h2f(h3));
                AH[q*2+0] = (u32)h0 | ((u32)h1 << 16);
                AH[q*2+1] = (u32)h2 | ((u32)h3 << 16);
                AL[q*2+0] = (u32)l0 | ((u32)l1 << 16);
                AL[q*2+1] = (u32)l2 | ((u32)l3 << 16);
            }
        }

        // ---- (C) wait B, then 64x128x128 GEMM, 3-term fp16 split ----
        CP_WAIT0();
        __syncthreads();

        #pragma unroll
        for (int ks = 0; ks < 8; ks++) {
            u32 k2 = (u32)ks * 32;                  // k0 * 2 bytes
            u32 aH0[4], aH1[4], aL0[4], aL1[4];
            LDSM4(aH0, aHb + k2);
            LDSM4(aH1, aHb + 16 * TS + k2);
            LDSM4(aL0, aLb + k2);
            LDSM4(aL1, aLb + 16 * TS + k2);
            #pragma unroll
            for (int nh = 0; nh < 2; nh++) {
                u32 bH[4], bL[4];
                LDSM4(bH, bHb + (u32)nh * 16 * TS + k2);
                LDSM4(bL, bLb + (u32)nh * 16 * TS + k2);
                int n0 = nh * 2, n1 = nh * 2 + 1;
                MMA16816(acc[0][n0], aH0, bH[0], bH[1]);
                MMA16816(acc[0][n0], aL0, bH[0], bH[1]);
                MMA16816(acc[0][n0], aH0, bL[0], bL[1]);
                MMA16816(acc[1][n0], aH1, bH[0], bH[1]);
                MMA16816(acc[1][n0], aL1, bH[0], bH[1]);
                MMA16816(acc[1][n0], aH1, bL[0], bL[1]);
                MMA16816(acc[0][n1], aH0, bH[2], bH[3]);
                MMA16816(acc[0][n1], aL0, bH[2], bH[3]);
                MMA16816(acc[0][n1], aH0, bL[2], bL[3]);
                MMA16816(acc[1][n1], aH1, bH[2], bH[3]);
                MMA16816(acc[1][n1], aL1, bH[2], bH[3]);
                MMA16816(acc[1][n1], aH1, bL[2], bL[3]);
            }
        }
    }

    if (cur_t >= 0) flush_acc(acc, cur_t, warp, lane);
}

// ---------------- reduce slabs + bias (+relu) ----------------
__global__ void reduce_kernel(const float* __restrict__ bias,
                              float* __restrict__ out, int do_relu) {
    int i = blockIdx.x * blockDim.x + threadIdx.x;
    const int n4 = N_NODES * D / 4;
    if (i >= n4) return;
    const float4* p4 = (const float4*)g_partial;
    float4 s = p4[i];
    #pragma unroll
    for (int k = 1; k < NSLAB; k++) {
        float4 t = p4[i + (size_t)k * n4];
        s.x += t.x; s.y += t.y; s.z += t.z; s.w += t.w;
    }
    float4 b = ((const float4*)bias)[i & 31];
    s.x += b.x; s.y += b.y; s.z += b.z; s.w += b.w;
    if (do_relu) {
        s.x = fmaxf(s.x, 0.f); s.y = fmaxf(s.y, 0.f);
        s.z = fmaxf(s.z, 0.f); s.w = fmaxf(s.w, 0.f);
    }
    ((float4*)out)[i] = s;
}

// ---------------- scoring: warp per batch item ----------------
__global__ void score_kernel(const int* __restrict__ batch,
                             const float* __restrict__ xn,
                             const float* __restrict__ rels,
                             float* __restrict__ out) {
    int w = (blockIdx.x * blockDim.x + threadIdx.x) >> 5;
    int lane = threadIdx.x & 31;
    if (w >= N_BATCH) return;
    int bs = batch[w*3+0], bp = batch[w*3+1], bo = batch[w*3+2];
    float4 a = ((const float4*)(xn + (size_t)bs * D))[lane];
    float4 r = ((const float4*)(rels + (size_t)bp * D))[lane];
    float4 c = ((const float4*)(xn + (size_t)bo * D))[lane];
    float s = a.x*r.x*c.x + a.y*r.y*c.y + a.z*r.z*c.z + a.w*r.w*c.w;
    #pragma unroll
    for (int o = 16; o; o >>= 1) s += __shfl_xor_sync(0xffffffffu, s, o);
    if (lane == 0) out[w] = s;
}

// ---------------- launch ----------------
extern "C" void kernel_launch(void* const* d_in, const int* in_sizes, int n_in,
                              void* d_out, int out_size) {
    const int*   graph = (const int*)d_in[0];
    const int*   batch = (const int*)d_in[1];
    const float* x0    = (const float*)d_in[2];
    const float* W1    = (const float*)d_in[3];
    const float* b1    = (const float*)d_in[4];
    const float* W2    = (const float*)d_in[5];
    const float* b2    = (const float*)d_in[6];
    const float* rels  = (const float*)d_in[7];
    float* out = (float*)d_out;

    void *p_h1 = nullptr, *p_h2 = nullptr, *p_bt1 = nullptr, *p_bt2 = nullptr;
    cudaGetSymbolAddress(&p_h1, g_h1);
    cudaGetSymbolAddress(&p_h2, g_h2);
    cudaGetSymbolAddress(&p_bt1, g_Bt1);
    cudaGetSymbolAddress(&p_bt2, g_Bt2);
    float* h1 = (float*)p_h1;
    float* h2 = (float*)p_h2;
    u16* bt1 = (u16*)p_bt1;
    u16* bt2 = (u16*)p_bt2;

    cudaFuncSetAttribute(layer_mega_kernel,
                         cudaFuncAttributeMaxDynamicSharedMemorySize, SMEM_TOT);

    const int zp_grid = (NSLAB * N_NODES * D / 4 + 255) / 256;
    const int rd_grid = (N_NODES * D / 4 + 255) / 256;

    // launches 1-3: W conversions + partial zero (layer kernel lands in slot 4)
    convert_w_kernel<<<R_AUG, 256>>>(W1, bt1);
    convert_w_kernel<<<R_AUG, 256>>>(W2, bt2);
    zero_partial_kernel<<<zp_grid, 256>>>();

    // layer 1 (builds CSR internally via grid barriers; 296 CTAs = 2/SM)
    layer_mega_kernel<<<NCTA, 256, SMEM_TOT>>>(x0, graph, bt1, 1);
    reduce_kernel<<<rd_grid, 256>>>(b1, h1, 1);

    // layer 2
    zero_partial_kernel<<<zp_grid, 256>>>();
    layer_mega_kernel<<<NCTA, 256, SMEM_TOT>>>(h1, graph, bt2, 0);
    reduce_kernel<<<rd_grid, 256>>>(b2, h2, 0);

    // scoring
    score_kernel<<<(N_BATCH * 32) / 256, 256>>>(batch, h2, rels, out);
}

// round 12
// speedup vs baseline: 1.4489x; 1.2730x over previous
#include <cuda_runtime.h>
#include <cuda_fp16.h>

// ---------------- problem constants ----------------
#define N_NODES 10000
#define N_RELS  50
#define R_AUG   101                    // 2*N_RELS + 1
#define D       128
#define N_EDGES 320000
#define E_AUG   (2*N_EDGES + N_NODES)  // 650000
#define N_SEG   (R_AUG * N_NODES)      // 1010000
#define N_BATCH 65536

// persistent layer config: 3 CTAs/SM, M-tile 64
#define TM      64
#define NTILES  ((N_NODES + TM - 1) / TM)          // 157
#define NITEMS  (NTILES * R_AUG)                   // 15857
#define NCTA    444
#define WPC     ((NITEMS + NCTA - 1) / NCTA)       // 36
#define NSLAB   4
#define SEG_CHUNK ((N_SEG + NCTA - 1) / NCTA)      // 2275

// fp16 tile row stride: 128 + 8 pad = 136 halves = 272 bytes
#define TS      272
#define APLANE  (64 * TS)                           // 17408
#define BPLANE  (128 * TS)                          // 34816

// smem layout (bytes)
#define OFF_AH   0                                  // A hi [64][136]
#define OFF_AL   APLANE                             // A lo
#define OFF_B    (2*APLANE)                         // B fp16 [128][136]
#define SMEM_TOT (2*APLANE + BPLANE + 64)           // 69,696 (~68.1 KB) -> 3/SM

typedef unsigned long long u64;
typedef unsigned int u32;
typedef unsigned short u16;

// ---------------- static device scratch ----------------
__device__ int   g_deg[N_SEG];
__device__ int   g_rowptr[N_SEG + 1];
__device__ int   g_cursor[N_SEG];
__device__ int   g_ctasum[NCTA];
__device__ int   g_csr[E_AUG];                         // src only
__device__ u16   g_Bt1[(size_t)R_AUG * 16384];         // layer1 W fp16, row=n col=k
__device__ u16   g_Bt2[(size_t)R_AUG * 16384];         // layer2 W
__device__ float g_h1[N_NODES * D];
__device__ float g_h2[N_NODES * D];
__device__ float g_partial[(size_t)NSLAB * N_NODES * D];
__device__ unsigned g_bcnt[8];                         // grid barrier counters (self-reset)
__device__ unsigned g_brel[8];                         // grid barrier release epochs (monotonic)

// ---------------- small helpers ----------------
__device__ __forceinline__ u32 smem_u32(const void* p) {
    u32 a;
    asm("{ .reg .u64 t; cvta.to.shared.u64 t, %1; cvt.u32.u64 %0, t; }" : "=r"(a) : "l"(p));
    return a;
}
__device__ __forceinline__ u16 f2h(float v) {
    u16 r; asm("cvt.rn.f16.f32 %0, %1;" : "=h"(r) : "f"(v)); return r;
}
__device__ __forceinline__ float h2f(u16 v) {
    float r; asm("cvt.f32.f16 %0, %1;" : "=f"(r) : "h"(v)); return r;
}

#define LDSM4(r, addr)                                                          \
    asm volatile("ldmatrix.sync.aligned.m8n8.x4.shared.b16 {%0,%1,%2,%3}, [%4];"\
        : "=r"((r)[0]), "=r"((r)[1]), "=r"((r)[2]), "=r"((r)[3]) : "r"(addr))

#define MMA16816(c, a, b0_, b1_)                                                \
    asm volatile("mma.sync.aligned.m16n8k16.row.col.f32.f16.f16.f32 "           \
        "{%0,%1,%2,%3}, {%4,%5,%6,%7}, {%8,%9}, {%0,%1,%2,%3};"                 \
        : "+f"((c)[0]), "+f"((c)[1]), "+f"((c)[2]), "+f"((c)[3])                \
        : "r"((a)[0]), "r"((a)[1]), "r"((a)[2]), "r"((a)[3]), "r"(b0_), "r"(b1_))

#define CP_ASYNC16(dst, src)                                                    \
    asm volatile("cp.async.cg.shared.global [%0], [%1], 16;" :: "r"(dst), "l"(src))
#define CP_COMMIT() asm volatile("cp.async.commit_group;" ::: "memory")
#define CP_WAIT0()  asm volatile("cp.async.wait_group 0;" ::: "memory")

// ---- replay-safe software grid barrier (all NCTA CTAs co-resident: 3/SM) ----
__device__ __forceinline__ void grid_bar(int slot) {
    __threadfence();
    __syncthreads();
    if (threadIdx.x == 0) {
        volatile unsigned* rel = (volatile unsigned*)&g_brel[slot];
        unsigned e0 = *rel;
        unsigned t = atomicAdd(&g_bcnt[slot], 1u);
        if (t == NCTA - 1) {
            g_bcnt[slot] = 0;
            __threadfence();
            atomicAdd(&g_brel[slot], 1u);
        } else {
            while (*rel == e0) { }
        }
        __threadfence();
    }
    __syncthreads();
}

// ---- block exclusive scan over 256 ints; returns exclusive, sets total ----
__device__ __forceinline__ int block_excl_scan(int v, int* ssc, int& total) {
    int lane = threadIdx.x & 31, w = threadIdx.x >> 5;
    int x = v;
    #pragma unroll
    for (int o = 1; o < 32; o <<= 1) {
        int y = __shfl_up_sync(0xffffffffu, x, o);
        if (lane >= o) x += y;
    }
    if (lane == 31) ssc[w] = x;
    __syncthreads();
    if (w == 0) {
        int tval = (lane < 8) ? ssc[lane] : 0;
        #pragma unroll
        for (int o = 1; o < 8; o <<= 1) {
            int y = __shfl_up_sync(0xffffffffu, tval, o);
            if (lane >= o) tval += y;
        }
        if (lane < 8) ssc[lane] = tval;    // inclusive warp totals
    }
    __syncthreads();
    int wbase = (w > 0) ? ssc[w - 1] : 0;
    total = ssc[7];
    __syncthreads();
    return wbase + x - v;
}

__device__ __forceinline__ void aug_edge(const int* __restrict__ g, int e,
                                         int& seg, int& src) {
    if (e < N_EDGES) {
        int s = g[e*3+0], p = g[e*3+1], o = g[e*3+2];
        seg = p * N_NODES + o;  src = s;
    } else if (e < 2*N_EDGES) {
        int e2 = e - N_EDGES;
        int s = g[e2*3+0], p = g[e2*3+1], o = g[e2*3+2];
        seg = (p + N_RELS) * N_NODES + s;  src = o;
    } else {
        int i = e - 2*N_EDGES;
        seg = 2*N_RELS*N_NODES + i;  src = i;
    }
}

// ---------------- W -> fp16 B^T plane (row=n, col=k) ----------------
__global__ void convert_w_kernel(const float* __restrict__ W, u16* __restrict__ Bt) {
    int r = blockIdx.x;
    const float* Wr = W + (size_t)r * (D * D);
    u16* B = Bt + (size_t)r * 16384;
    for (int idx = threadIdx.x; idx < D * D; idx += blockDim.x) {
        int k = idx >> 7, n = idx & 127;
        B[n * D + k] = f2h(Wr[k * D + n]);
    }
}

__global__ void zero_partial_kernel() {
    int i = blockIdx.x * blockDim.x + threadIdx.x;
    const int n4 = NSLAB * N_NODES * D / 4;
    if (i < n4) ((float4*)g_partial)[i] = make_float4(0.f, 0.f, 0.f, 0.f);
}

// ---------------- flush register accumulators to a partial slab ----------------
__device__ __forceinline__ void flush_acc(float acc[2][4][4], int cur_t,
                                          int warp, int lane) {
    int slab_i = blockIdx.x - (cur_t * R_AUG) / WPC;
    float* slab = g_partial + (size_t)slab_i * (N_NODES * D);
    int wm = warp & 1, wn = warp >> 1;
    int r0 = cur_t * TM + wm * 32 + (lane >> 2);
    int cb = wn * 32 + (lane & 3) * 2;
    #pragma unroll
    for (int mf = 0; mf < 2; mf++) {
        int rowA = r0 + mf * 16;
        int rowB = rowA + 8;
        #pragma unroll
        for (int nf = 0; nf < 4; nf++) {
            int col = cb + nf * 8;
            if (rowA < N_NODES)
                *(float2*)(slab + (size_t)rowA * D + col) =
                    make_float2(acc[mf][nf][0], acc[mf][nf][1]);
            if (rowB < N_NODES)
                *(float2*)(slab + (size_t)rowB * D + col) =
                    make_float2(acc[mf][nf][2], acc[mf][nf][3]);
        }
    }
}

// ---- cp.async prefetch of one relation's fp16 B tile (single plane) ----
__device__ __forceinline__ void prefetch_B(u32 smbuf, const u16* __restrict__ Bt, int r) {
    const char* src_base = (const char*)(Bt + (size_t)r * 16384);
    int tid = threadIdx.x;
    #pragma unroll
    for (int q = 0; q < 8; q++) {
        int idx = tid + q * 256;           // 0..2047 16B chunks
        int row = idx >> 4, c16 = idx & 15;
        u32 dst = smbuf + row * TS + c16 * 16;
        const char* src = src_base + row * 256 + c16 * 16;
        CP_ASYNC16(dst, src);
    }
}

// ---------------- persistent mega kernel: (optional CSR build) + layer ----------------
extern "C" __global__ void __launch_bounds__(256, 3)
layer_mega_kernel(const float* __restrict__ x, const int* __restrict__ graph,
                  const u16* __restrict__ Bt, int build_csr) {
    extern __shared__ char smem[];
    __shared__ int ssc[16];
    __shared__ int sbase;
    u32 smb = smem_u32(smem);

    int tid  = threadIdx.x;
    int bid  = blockIdx.x;
    int gtid = bid * 256 + tid;
    const int gstride = NCTA * 256;

    // ================= CSR build (layer-1 instance only) =================
    if (build_csr) {
        // P0: zero degrees
        for (int i = gtid; i < N_SEG; i += gstride) g_deg[i] = 0;
        grid_bar(0);
        // P1: histogram
        for (int e = gtid; e < E_AUG; e += gstride) {
            int seg, src;
            aug_edge(graph, e, seg, src);
            atomicAdd(&g_deg[seg], 1);
        }
        grid_bar(1);
        // P2: per-CTA degree sum over contiguous chunk
        int s0 = bid * SEG_CHUNK;
        int s1 = min(s0 + SEG_CHUNK, N_SEG);
        {
            int lsum = 0;
            for (int i = s0 + tid; i < s1; i += 256) lsum += g_deg[i];
            #pragma unroll
            for (int o = 16; o; o >>= 1) lsum += __shfl_xor_sync(0xffffffffu, lsum, o);
            if ((tid & 31) == 0) ssc[tid >> 5] = lsum;
            __syncthreads();
            if (tid < 8) {
                int v = ssc[tid];
                #pragma unroll
                for (int o = 4; o; o >>= 1) v += __shfl_xor_sync(0xffu, v, o);
                if (tid == 0) g_ctasum[bid] = v;
            }
            __syncthreads();
        }
        grid_bar(2);
        // P3: CTA base via pairwise block scan of 444 CTA sums (2 per thread)
        {
            int va = 0, vp = 0;
            if (tid < NCTA / 2) {
                va = g_ctasum[2 * tid];
                vp = va + g_ctasum[2 * tid + 1];
            }
            int tot;
            int ex = block_excl_scan(vp, ssc, tot);
            if (2 * tid == bid) sbase = ex;
            if (2 * tid + 1 == bid) sbase = ex + va;
            __syncthreads();
            int run = sbase;
            const int nchunk = (SEG_CHUNK + 255) / 256;
            for (int c = 0; c < nchunk; c++) {
                int gi = s0 + c * 256 + tid;
                int dv = (gi < s1) ? g_deg[gi] : 0;
                int ctot;
                int cex = block_excl_scan(dv, ssc, ctot);
                if (gi < s1) {
                    int rp = run + cex;
                    g_rowptr[gi] = rp;
                    g_cursor[gi] = rp;
                }
                run += ctot;
            }
            if (bid == NCTA - 1 && tid == 0) g_rowptr[N_SEG] = E_AUG;
        }
        grid_bar(3);
        // P4: scatter
        for (int e = gtid; e < E_AUG; e += gstride) {
            int seg, src;
            aug_edge(graph, e, seg, src);
            int pos = atomicAdd(&g_cursor[seg], 1);
            g_csr[pos] = src;
        }
        grid_bar(4);
    }

    // ================= layer items =================
    int warp = tid >> 5, lane = tid & 31;
    int wm = warp & 1, wn = warp >> 1;

    // ldmatrix per-lane row offsets (bytes) within a tile
    u32 rowa = (u32)(wm * 32 + (lane & 15)) * TS + (u32)((lane >> 4) << 3) * 2;
    u32 rowb = (u32)(wn * 32 + ((lane >> 4) << 3) + (lane & 7)) * TS
             + (u32)(((lane >> 3) & 1) << 3) * 2;
    u32 aHb = smb + OFF_AH + rowa, aLb = smb + OFF_AL + rowa;
    u32 bHb = smb + OFF_B + rowb;

    int bsub = tid & 3;            // 32-dim chunk
    int brow = tid >> 2;           // row 0..63

    float acc[2][4][4];
    #pragma unroll
    for (int i = 0; i < 2; i++)
        #pragma unroll
        for (int j = 0; j < 4; j++)
            #pragma unroll
            for (int q = 0; q < 4; q++) acc[i][j][q] = 0.f;

    int i0 = bid * WPC;
    int i1 = min(i0 + WPC, NITEMS);
    if (i0 >= i1) return;

    int cur_t = -1;

    for (int it = i0; it < i1; ++it) {
        int t = it / R_AUG;
        int r = it - t * R_AUG;
        int tb = t * TM;
        int nrows = min(TM, N_NODES - tb);
        int segbase = r * N_NODES + tb;

        if (t != cur_t) {
            if (cur_t >= 0) {
                flush_acc(acc, cur_t, warp, lane);
                #pragma unroll
                for (int i = 0; i < 2; i++)
                    #pragma unroll
                    for (int j = 0; j < 4; j++)
                        #pragma unroll
                        for (int q = 0; q < 4; q++) acc[i][j][q] = 0.f;
            }
            cur_t = t;
        }

        __syncthreads();   // previous GEMM done reading A & B tiles

        // ---- (A) kick B prefetch (buffer free now), overlaps the build ----
        prefetch_B(smb + OFF_B, Bt, r);
        CP_COMMIT();

        // ---- (B) build + convert A tiles, register-resident, no atomics ----
        {
            float4 a[8];
            #pragma unroll
            for (int q = 0; q < 8; q++) a[q] = make_float4(0.f, 0.f, 0.f, 0.f);
            int deg = 0;
            if (brow < nrows) {
                int seg = segbase + brow;
                int s = g_rowptr[seg], e = g_rowptr[seg + 1];
                deg = e - s;
                for (int j = s; j < e; ++j) {
                    int src = g_csr[j];
                    const float4* v = (const float4*)(x + (size_t)src * D + (bsub << 5));
                    #pragma unroll
                    for (int q = 0; q < 8; q++) {
                        float4 w = v[q];
                        a[q].x += w.x; a[q].y += w.y; a[q].z += w.z; a[q].w += w.w;
                    }
                }
            }
            float nrm = 1.0f / fmaxf((float)deg, 1.0f);
            u32* AH = (u32*)(smem + OFF_AH + brow * TS + (bsub << 6));
            u32* AL = (u32*)(smem + OFF_AL + brow * TS + (bsub << 6));
            #pragma unroll
            for (int q = 0; q < 8; q++) {
                float v0 = a[q].x * nrm, v1 = a[q].y * nrm;
                float v2 = a[q].z * nrm, v3 = a[q].w * nrm;
                u16 h0 = f2h(v0), h1 = f2h(v1), h2 = f2h(v2), h3 = f2h(v3);
                u16 l0 = f2h(v0 - h2f(h0)), l1 = f2h(v1 - h2f(h1));
                u16 l2 = f2h(v2 - h2f(h2)), l3 = f2h(v3 - h2f(h3));
                AH[q*2+0] = (u32)h0 | ((u32)h1 << 16);
                AH[q*2+1] = (u32)h2 | ((u32)h3 << 16);
                AL[q*2+0] = (u32)l0 | ((u32)l1 << 16);
                AL[q*2+1] = (u32)l2 | ((u32)l3 << 16);
            }
        }

        // ---- (C) wait B, then 64x128x128 GEMM, 2-term fp16 split ----
        CP_WAIT0();
        __syncthreads();

        #pragma unroll
        for (int ks = 0; ks < 8; ks++) {
            u32 k2 = (u32)ks * 32;                  // k0 * 2 bytes
            u32 aH0[4], aH1[4], aL0[4], aL1[4];
            LDSM4(aH0, aHb + k2);
            LDSM4(aH1, aHb + 16 * TS + k2);
            LDSM4(aL0, aLb + k2);
            LDSM4(aL1, aLb + 16 * TS + k2);
            #pragma unroll
            for (int nh = 0; nh < 2; nh++) {
                u32 bH[4];
                LDSM4(bH, bHb + (u32)nh * 16 * TS + k2);
                int n0 = nh * 2, n1 = nh * 2 + 1;
                MMA16816(acc[0][n0], aH0, bH[0], bH[1]);
                MMA16816(acc[0][n0], aL0, bH[0], bH[1]);
                MMA16816(acc[1][n0], aH1, bH[0], bH[1]);
                MMA16816(acc[1][n0], aL1, bH[0], bH[1]);
                MMA16816(acc[0][n1], aH0, bH[2], bH[3]);
                MMA16816(acc[0][n1], aL0, bH[2], bH[3]);
                MMA16816(acc[1][n1], aH1, bH[2], bH[3]);
                MMA16816(acc[1][n1], aL1, bH[2], bH[3]);
            }
        }
    }

    if (cur_t >= 0) flush_acc(acc, cur_t, warp, lane);
}

// ---------------- reduce slabs + bias (+relu) ----------------
__global__ void reduce_kernel(const float* __restrict__ bias,
                              float* __restrict__ out, int do_relu) {
    int i = blockIdx.x * blockDim.x + threadIdx.x;
    const int n4 = N_NODES * D / 4;
    if (i >= n4) return;
    const float4* p4 = (const float4*)g_partial;
    float4 s = p4[i];
    #pragma unroll
    for (int k = 1; k < NSLAB; k++) {
        float4 t = p4[i + (size_t)k * n4];
        s.x += t.x; s.y += t.y; s.z += t.z; s.w += t.w;
    }
    float4 b = ((const float4*)bias)[i & 31];
    s.x += b.x; s.y += b.y; s.z += b.z; s.w += b.w;
    if (do_relu) {
        s.x = fmaxf(s.x, 0.f); s.y = fmaxf(s.y, 0.f);
        s.z = fmaxf(s.z, 0.f); s.w = fmaxf(s.w, 0.f);
    }
    ((float4*)out)[i] = s;
}

// ---------------- scoring: warp per batch item ----------------
__global__ void score_kernel(const int* __restrict__ batch,
                             const float* __restrict__ xn,
                             const float* __restrict__ rels,
                             float* __restrict__ out) {
    int w = (blockIdx.x * blockDim.x + threadIdx.x) >> 5;
    int lane = threadIdx.x & 31;
    if (w >= N_BATCH) return;
    int bs = batch[w*3+0], bp = batch[w*3+1], bo = batch[w*3+2];
    float4 a = ((const float4*)(xn + (size_t)bs * D))[lane];
    float4 r = ((const float4*)(rels + (size_t)bp * D))[lane];
    float4 c = ((const float4*)(xn + (size_t)bo * D))[lane];
    float s = a.x*r.x*c.x + a.y*r.y*c.y + a.z*r.z*c.z + a.w*r.w*c.w;
    #pragma unroll
    for (int o = 16; o; o >>= 1) s += __shfl_xor_sync(0xffffffffu, s, o);
    if (lane == 0) out[w] = s;
}

// ---------------- launch ----------------
extern "C" void kernel_launch(void* const* d_in, const int* in_sizes, int n_in,
                              void* d_out, int out_size) {
    const int*   graph = (const int*)d_in[0];
    const int*   batch = (const int*)d_in[1];
    const float* x0    = (const float*)d_in[2];
    const float* W1    = (const float*)d_in[3];
    const float* b1    = (const float*)d_in[4];
    const float* W2    = (const float*)d_in[5];
    const float* b2    = (const float*)d_in[6];
    const float* rels  = (const float*)d_in[7];
    float* out = (float*)d_out;

    void *p_h1 = nullptr, *p_h2 = nullptr, *p_bt1 = nullptr, *p_bt2 = nullptr;
    cudaGetSymbolAddress(&p_h1, g_h1);
    cudaGetSymbolAddress(&p_h2, g_h2);
    cudaGetSymbolAddress(&p_bt1, g_Bt1);
    cudaGetSymbolAddress(&p_bt2, g_Bt2);
    float* h1 = (float*)p_h1;
    float* h2 = (float*)p_h2;
    u16* bt1 = (u16*)p_bt1;
    u16* bt2 = (u16*)p_bt2;

    cudaFuncSetAttribute(layer_mega_kernel,
                         cudaFuncAttributeMaxDynamicSharedMemorySize, SMEM_TOT);

    const int zp_grid = (NSLAB * N_NODES * D / 4 + 255) / 256;
    const int rd_grid = (N_NODES * D / 4 + 255) / 256;

    // launches 1-3: W conversions + partial zero (layer kernel lands in slot 4)
    convert_w_kernel<<<R_AUG, 256>>>(W1, bt1);
    convert_w_kernel<<<R_AUG, 256>>>(W2, bt2);
    zero_partial_kernel<<<zp_grid, 256>>>();

    // layer 1 (builds CSR internally via grid barriers; 444 CTAs = 3/SM)
    layer_mega_kernel<<<NCTA, 256, SMEM_TOT>>>(x0, graph, bt1, 1);
    reduce_kernel<<<rd_grid, 256>>>(b1, h1, 1);

    // layer 2
    zero_partial_kernel<<<zp_grid, 256>>>();
    layer_mega_kernel<<<NCTA, 256, SMEM_TOT>>>(h1, graph, bt2, 0);
    reduce_kernel<<<rd_grid, 256>>>(b2, h2, 0);

    // scoring
    score_kernel<<<(N_BATCH * 32) / 256, 256>>>(batch, h2, rels, out);
}